// round 6
// baseline (speedup 1.0000x reference)
#include <cuda_runtime.h>
#include <cstdint>

// Problem constants
#define Bq     8
#define NIN    512
#define NOUT   1024
#define Cc     16
#define OUTC   32
#define KW     5

// Conv tiling
#define CNTILE 32
#define CTHREADS 128

// Fused gauss+linear tiling
#define MTILE  64                 // m targets per block (4 per thread)
#define MT     (NOUT / MTILE)     // 16
#define GWARPS 16
#define NPW    (NIN / GWARPS)     // 32
#define GTHREADS (GWARPS * 32)    // 512
#define RSETS  8                  // partial sets in smem (staged reduce)

#define LOG2E 1.4426950408889634f

__device__ float g_rt[Bq * NIN * Cc];   // conv output [b][n][c]

__device__ __forceinline__ void ffma2(uint64_t& d, uint64_t a, uint64_t b) {
    asm("fma.rn.f32x2 %0, %1, %2, %0;" : "+l"(d) : "l"(a), "l"(b));
}
__device__ __forceinline__ uint64_t pack2(float lo, float hi) {
    uint64_t r; asm("mov.b64 %0, {%1, %2};" : "=l"(r) : "f"(lo), "f"(hi)); return r;
}
__device__ __forceinline__ void unpack2(uint64_t v, float& lo, float& hi) {
    asm("mov.b64 {%0, %1}, %2;" : "=f"(lo), "=f"(hi) : "l"(v));
}
__device__ __forceinline__ float ex2a(float x) {
    float r; asm("ex2.approx.f32 %0, %1;" : "=f"(r) : "f"(x)); return r;
}

// ---------------------------------------------------------------------------
// Kernel 1: Conv1d (NCH, OIH, SAME pad=2) + bias -> g_rt[b][n][c]
// grid (16, 8) = 128 blocks, block 128.
// ---------------------------------------------------------------------------
__global__ void conv_kernel(const float* __restrict__ r,
                            const float* __restrict__ w,
                            const float* __restrict__ bias) {
    __shared__ float sr[Cc][CNTILE + 4];
    __shared__ float sws[Cc * KW * Cc];   // [ci][k][c_out]
    __shared__ float sb[Cc];

    const int b  = blockIdx.y;
    const int n0 = blockIdx.x * CNTILE;
    const int t  = threadIdx.x;

    for (int i = t; i < Cc * (CNTILE + 4); i += CTHREADS) {
        int ci = i / (CNTILE + 4);
        int j  = i % (CNTILE + 4);
        int n  = n0 + j - 2;
        sr[ci][j] = (n >= 0 && n < NIN) ? r[((size_t)b * Cc + ci) * NIN + n] : 0.0f;
    }
    for (int i = t; i < Cc * Cc * KW; i += CTHREADS) {
        int c  = i / (Cc * KW);
        int rm = i % (Cc * KW);
        int ci = rm / KW;
        int k  = rm % KW;
        sws[(ci * KW + k) * Cc + c] = w[i];
    }
    if (t < Cc) sb[t] = bias[t];
    __syncthreads();

    const int nl = t & (CNTILE - 1);
    const int cg = t >> 5;            // 0..3

    float4 a;
    a.x = sb[cg * 4 + 0]; a.y = sb[cg * 4 + 1];
    a.z = sb[cg * 4 + 2]; a.w = sb[cg * 4 + 3];

    #pragma unroll
    for (int k = 0; k < KW; k++) {
        #pragma unroll
        for (int ci = 0; ci < Cc; ci++) {
            float v = sr[ci][nl + k];
            float4 wv = *reinterpret_cast<const float4*>(&sws[(ci * KW + k) * Cc + cg * 4]);
            a.x += v * wv.x; a.y += v * wv.y; a.z += v * wv.z; a.w += v * wv.w;
        }
    }

    *reinterpret_cast<float4*>(g_rt + ((size_t)b * NIN + n0 + nl) * Cc + cg * 4) = a;
}

// ---------------------------------------------------------------------------
// Kernel 2: fused Gaussian transform + staged reduce + pointwise linear.
// grid (MT, B) = (16, 8) = 128 blocks, block 512 (16 warps).
// Lane mapping: mlane = lane>>1 (16 m-lanes), cg = lane&1 (channel half).
// Thread owns 4 m (mlane, +16, +32, +48) x 8 channels (cg*8..cg*8+7).
// Per warp per n: 1 broadcast LDS.32 (xn) + 1 LDS.128 (r slice, 2 distinct
// addresses) + 4 ex2 + 16 FFMA2 covering 64 m x 16 c.
// ---------------------------------------------------------------------------
__global__ void __launch_bounds__(GTHREADS, 1)
gauss_lin_kernel(const float* __restrict__ xc,
                 const float* __restrict__ xt,
                 const float* __restrict__ sigma,
                 const float* __restrict__ lw,
                 const float* __restrict__ lb,
                 float* __restrict__ out) {
    __shared__ float shx[NIN];                                 // 2 KB
    __shared__ __align__(16) float shrt[NIN][Cc];              // 32 KB
    __shared__ __align__(16) float red[RSETS * MTILE * Cc];    // 32 KB
    __shared__ float shlw[OUTC * Cc];                          // 2 KB
    __shared__ float sh_nh[Cc];
    __shared__ int   sh_alleq;

    const int b  = blockIdx.y;
    const int mt = blockIdx.x;
    const int t  = threadIdx.x;
    const int lane = t & 31;
    const int wid  = t >> 5;
    const int mlane = lane >> 1;      // 0..15
    const int cg    = lane & 1;       // channel half
    const int c8    = cg * 8;

    if (t < Cc) {
        float sg = sigma[t];
        sh_nh[t] = -0.5f * expf(-2.0f * sg) * LOG2E;  // fold log2e for ex2
    }
    if (t == 0) {
        float s0 = sigma[0];
        int eq = 1;
        #pragma unroll
        for (int c = 1; c < Cc; c++) eq &= (sigma[c] == s0);
        sh_alleq = eq;
    }
    for (int i = t; i < NIN; i += GTHREADS) shx[i] = xc[(size_t)b * NIN + i];
    {
        const float4* src = reinterpret_cast<const float4*>(g_rt + (size_t)b * NIN * Cc);
        float4* dst = reinterpret_cast<float4*>(&shrt[0][0]);
        #pragma unroll
        for (int i = t; i < NIN * Cc / 4; i += GTHREADS) dst[i] = src[i];
    }
    for (int i = t; i < OUTC * Cc; i += GTHREADS) shlw[i] = lw[i];
    __syncthreads();

    // thread's 4 m-targets
    const int mb = mt * MTILE + mlane;
    float xm0 = xt[(size_t)b * NOUT + mb];
    float xm1 = xt[(size_t)b * NOUT + mb + 16];
    float xm2 = xt[(size_t)b * NOUT + mb + 32];
    float xm3 = xt[(size_t)b * NOUT + mb + 48];

    // acc[k][p]: m-target k, channel-pair p (channels c8+2p, c8+2p+1)
    uint64_t acc[4][4];
    #pragma unroll
    for (int k = 0; k < 4; k++)
        #pragma unroll
        for (int p = 0; p < 4; p++) acc[k][p] = 0ull;

    const int n0 = wid * NPW;

    if (sh_alleq) {
        const float nh = sh_nh[0];
        ulonglong2 q = *reinterpret_cast<const ulonglong2*>(&shrt[n0][c8]);
        float xn = shx[n0];
        #pragma unroll 4
        for (int i = 0; i < NPW; i++) {
            // prefetch next n
            ulonglong2 qn;
            float xnn;
            if (i + 1 < NPW) {
                qn  = *reinterpret_cast<const ulonglong2*>(&shrt[n0 + i + 1][c8]);
                xnn = shx[n0 + i + 1];
            }
            float d0 = xm0 - xn, d1 = xm1 - xn, d2 = xm2 - xn, d3 = xm3 - xn;
            float e0 = ex2a(d0 * d0 * nh);
            float e1 = ex2a(d1 * d1 * nh);
            float e2 = ex2a(d2 * d2 * nh);
            float e3 = ex2a(d3 * d3 * nh);
            uint64_t e0p = pack2(e0, e0);
            uint64_t e1p = pack2(e1, e1);
            uint64_t e2p = pack2(e2, e2);
            uint64_t e3p = pack2(e3, e3);
            ffma2(acc[0][0], e0p, q.x);
            { uint64_t hi = q.y; // split 32B slice: q.x = pairs 0-1? layout below
              (void)hi; }
            // q covers 4 f32 pairs? No: ulonglong2 = 16B = 4 floats = 2 pairs.
            // Need 8 channels = 32B: load as two ulonglong2.
            ffma2(acc[1][0], e1p, q.x);
            ffma2(acc[2][0], e2p, q.x);
            ffma2(acc[3][0], e3p, q.x);
            ffma2(acc[0][1], e0p, q.y);
            ffma2(acc[1][1], e1p, q.y);
            ffma2(acc[2][1], e2p, q.y);
            ffma2(acc[3][1], e3p, q.y);
            ulonglong2 q2 = *reinterpret_cast<const ulonglong2*>(&shrt[n0 + i][c8 + 4]);
            ffma2(acc[0][2], e0p, q2.x);
            ffma2(acc[1][2], e1p, q2.x);
            ffma2(acc[2][2], e2p, q2.x);
            ffma2(acc[3][2], e3p, q2.x);
            ffma2(acc[0][3], e0p, q2.y);
            ffma2(acc[1][3], e1p, q2.y);
            ffma2(acc[2][3], e2p, q2.y);
            ffma2(acc[3][3], e3p, q2.y);
            q  = qn;
            xn = xnn;
        }
    } else {
        float nh[8];
        #pragma unroll
        for (int c = 0; c < 8; c++) nh[c] = sh_nh[c8 + c];
        for (int i = 0; i < NPW; i++) {
            const int n = n0 + i;
            const float xn = shx[n];
            const ulonglong2* rp = reinterpret_cast<const ulonglong2*>(&shrt[n][c8]);
            ulonglong2 qa = rp[0], qb = rp[1];
            float ds[4];
            ds[0] = (xm0 - xn) * (xm0 - xn);
            ds[1] = (xm1 - xn) * (xm1 - xn);
            ds[2] = (xm2 - xn) * (xm2 - xn);
            ds[3] = (xm3 - xn) * (xm3 - xn);
            #pragma unroll
            for (int k = 0; k < 4; k++) {
                float d = ds[k];
                uint64_t ep0 = pack2(ex2a(d * nh[0]), ex2a(d * nh[1]));
                uint64_t ep1 = pack2(ex2a(d * nh[2]), ex2a(d * nh[3]));
                uint64_t ep2 = pack2(ex2a(d * nh[4]), ex2a(d * nh[5]));
                uint64_t ep3 = pack2(ex2a(d * nh[6]), ex2a(d * nh[7]));
                ffma2(acc[k][0], ep0, qa.x);
                ffma2(acc[k][1], ep1, qa.y);
                ffma2(acc[k][2], ep2, qb.x);
                ffma2(acc[k][3], ep3, qb.y);
            }
        }
    }

    // --- staged reduction into RSETS=8 partial sets -------------------------
    // red layout: [set][m_local 0..63][c 0..15]; thread writes 4 m x 8 ch.
    if (wid >= RSETS) {
        const int set = wid - RSETS;
        #pragma unroll
        for (int k = 0; k < 4; k++) {
            float v[8];
            #pragma unroll
            for (int p = 0; p < 4; p++) unpack2(acc[k][p], v[2 * p], v[2 * p + 1]);
            float* rp = red + ((size_t)set * MTILE + mlane + 16 * k) * Cc + c8;
            *reinterpret_cast<float4*>(rp)     = make_float4(v[0], v[1], v[2], v[3]);
            *reinterpret_cast<float4*>(rp + 4) = make_float4(v[4], v[5], v[6], v[7]);
        }
    }
    __syncthreads();
    if (wid < RSETS) {
        #pragma unroll
        for (int k = 0; k < 4; k++) {
            float v[8];
            #pragma unroll
            for (int p = 0; p < 4; p++) unpack2(acc[k][p], v[2 * p], v[2 * p + 1]);
            float* rp = red + ((size_t)wid * MTILE + mlane + 16 * k) * Cc + c8;
            float4 o0 = *reinterpret_cast<const float4*>(rp);
            float4 o1 = *reinterpret_cast<const float4*>(rp + 4);
            *reinterpret_cast<float4*>(rp) =
                make_float4(o0.x + v[0], o0.y + v[1], o0.z + v[2], o0.w + v[3]);
            *reinterpret_cast<float4*>(rp + 4) =
                make_float4(o1.x + v[4], o1.y + v[5], o1.z + v[6], o1.w + v[7]);
        }
    }
    __syncthreads();

    // tree-reduce 8 sets into red[0..MTILE*Cc)
    {
        float4* rv = reinterpret_cast<float4*>(red);
        const int NV = MTILE * Cc / 4;   // 256 slots
        if (t < NV) {
            float4 s = rv[t];
            #pragma unroll
            for (int w = 1; w < RSETS; w++) {
                float4 p = rv[w * NV + t];
                s.x += p.x; s.y += p.y; s.z += p.z; s.w += p.w;
            }
            rv[t] = s;
        }
    }
    __syncthreads();

    // linear C -> OUT_C: thread t -> (ml = t>>3, 4 outputs at og=(t&7)*4)
    {
        const int ml = t >> 3;            // 0..63
        const int og = (t & 7) * 4;       // 0..28
        const float* z = red + ml * Cc;
        float4 o4;
        o4.x = __ldg(lb + og + 0); o4.y = __ldg(lb + og + 1);
        o4.z = __ldg(lb + og + 2); o4.w = __ldg(lb + og + 3);
        #pragma unroll
        for (int c = 0; c < Cc; c++) {
            float zc = z[c];
            o4.x += zc * shlw[(og + 0) * Cc + c];
            o4.y += zc * shlw[(og + 1) * Cc + c];
            o4.z += zc * shlw[(og + 2) * Cc + c];
            o4.w += zc * shlw[(og + 3) * Cc + c];
        }
        *reinterpret_cast<float4*>(
            out + (((size_t)b * NOUT) + mt * MTILE + ml) * OUTC + og) = o4;
    }
}

// ---------------------------------------------------------------------------
// Launch. Inputs (metadata order):
// 0 r (8,16,512) | 1 x_context (8,512,1) | 2 y_context (unused) |
// 3 x_target (8,1024,1) | 4 conv_w (16,16,5) | 5 conv_b (16) |
// 6 sigma (16) | 7 lin_w (32,16) | 8 lin_b (32)  -> out (8,1024,32) f32
// ---------------------------------------------------------------------------
extern "C" void kernel_launch(void* const* d_in, const int* in_sizes, int n_in,
                              void* d_out, int out_size) {
    const float* r      = (const float*)d_in[0];
    const float* xc     = (const float*)d_in[1];
    const float* xt     = (const float*)d_in[3];
    const float* conv_w = (const float*)d_in[4];
    const float* conv_b = (const float*)d_in[5];
    const float* sigma  = (const float*)d_in[6];
    const float* lin_w  = (const float*)d_in[7];
    const float* lin_b  = (const float*)d_in[8];
    float* out = (float*)d_out;

    conv_kernel<<<dim3(NIN / CNTILE, Bq), CTHREADS>>>(r, conv_w, conv_b);
    gauss_lin_kernel<<<dim3(MT, Bq), GTHREADS>>>(xc, xt, sigma, lin_w, lin_b, out);
}

// round 7
// speedup vs baseline: 1.2581x; 1.2581x over previous
#include <cuda_runtime.h>
#include <cstdint>

// Problem constants
#define Bq     8
#define NIN    512
#define NOUT   1024
#define Cc     16
#define OUTC   32
#define KW     5

// Conv tiling
#define CNTILE 32
#define CTHREADS 128

// Gauss-MMA tiling
#define MTILE  64                 // m per block
#define MT     (NOUT / MTILE)     // 16
#define GTHREADS 256              // 8 warps: 4 m-subtiles x 2 k-halves

#define LOG2E 1.4426950408889634f

__device__ float g_rt[Bq * NIN * Cc];   // conv output [b][n][c], tf32-rounded

__device__ __forceinline__ float ex2a(float x) {
    float r; asm("ex2.approx.f32 %0, %1;" : "=f"(r) : "f"(x)); return r;
}
__device__ __forceinline__ unsigned f2tf32(float x) {
    unsigned r; asm("cvt.rna.tf32.f32 %0, %1;" : "=r"(r) : "f"(x)); return r;
}
__device__ __forceinline__ void mma_tf32(float d[4], const unsigned a[4],
                                         unsigned b0, unsigned b1) {
    asm volatile(
        "mma.sync.aligned.m16n8k8.row.col.f32.tf32.tf32.f32 "
        "{%0,%1,%2,%3}, {%4,%5,%6,%7}, {%8,%9}, {%0,%1,%2,%3};"
        : "+f"(d[0]), "+f"(d[1]), "+f"(d[2]), "+f"(d[3])
        : "r"(a[0]), "r"(a[1]), "r"(a[2]), "r"(a[3]), "r"(b0), "r"(b1));
}

// ---------------------------------------------------------------------------
// Kernel 1: Conv1d (NCH, OIH, SAME pad=2) + bias -> g_rt[b][n][c] (tf32-rnd)
// grid (16, 8) = 128 blocks, block 128.
// ---------------------------------------------------------------------------
__global__ void conv_kernel(const float* __restrict__ r,
                            const float* __restrict__ w,
                            const float* __restrict__ bias) {
    __shared__ float sr[Cc][CNTILE + 4];
    __shared__ float sws[Cc * KW * Cc];   // [ci][k][c_out]
    __shared__ float sb[Cc];

    const int b  = blockIdx.y;
    const int n0 = blockIdx.x * CNTILE;
    const int t  = threadIdx.x;

    for (int i = t; i < Cc * (CNTILE + 4); i += CTHREADS) {
        int ci = i / (CNTILE + 4);
        int j  = i % (CNTILE + 4);
        int n  = n0 + j - 2;
        sr[ci][j] = (n >= 0 && n < NIN) ? r[((size_t)b * Cc + ci) * NIN + n] : 0.0f;
    }
    for (int i = t; i < Cc * Cc * KW; i += CTHREADS) {
        int c  = i / (Cc * KW);
        int rm = i % (Cc * KW);
        int ci = rm / KW;
        int k  = rm % KW;
        sws[(ci * KW + k) * Cc + c] = w[i];
    }
    if (t < Cc) sb[t] = bias[t];
    __syncthreads();

    const int nl = t & (CNTILE - 1);
    const int cg = t >> 5;            // 0..3

    float4 a;
    a.x = sb[cg * 4 + 0]; a.y = sb[cg * 4 + 1];
    a.z = sb[cg * 4 + 2]; a.w = sb[cg * 4 + 3];

    #pragma unroll
    for (int k = 0; k < KW; k++) {
        #pragma unroll
        for (int ci = 0; ci < Cc; ci++) {
            float v = sr[ci][nl + k];
            float4 wv = *reinterpret_cast<const float4*>(&sws[(ci * KW + k) * Cc + cg * 4]);
            a.x += v * wv.x; a.y += v * wv.y; a.z += v * wv.z; a.w += v * wv.w;
        }
    }

    // round to tf32 so the MMA B operand is exactly representable
    a.x = __uint_as_float(f2tf32(a.x));
    a.y = __uint_as_float(f2tf32(a.y));
    a.z = __uint_as_float(f2tf32(a.z));
    a.w = __uint_as_float(f2tf32(a.w));

    *reinterpret_cast<float4*>(g_rt + ((size_t)b * NIN + n0 + nl) * Cc + cg * 4) = a;
}

// ---------------------------------------------------------------------------
// Kernel 2: Gaussian transform as tf32 MMA + k-reduce + linear C->OUT_C.
// grid (MT, B) = (16, 8) = 128 blocks, block 256 (8 warps).
// Warp w: msub = w&3 (16 m), khalf = w>>2 (256 n). Per kstep (8 n):
// thread computes its 4 A-fragment exps in registers (zero memory for W);
// B fragments come from a conflict-free swizzled smem copy of rt.
// Swizzle: addr(n,c) = (n>>2)*64 + (c>>3)*32 + (n&3)*8 + (c&7).
// ---------------------------------------------------------------------------
__global__ void __launch_bounds__(GTHREADS, 1)
gauss_mma_kernel(const float* __restrict__ xc,
                 const float* __restrict__ xt,
                 const float* __restrict__ sigma,
                 const float* __restrict__ lw,
                 const float* __restrict__ lb,
                 float* __restrict__ out) {
    __shared__ __align__(16) float sB[NIN * Cc];        // 32 KB swizzled rt
    __shared__ float shx[NIN];                          // 2 KB
    __shared__ __align__(16) float zred[2][MTILE][Cc];  // 8 KB k-half partials
    __shared__ float shlw[OUTC * Cc];                   // 2 KB
    __shared__ float sh_nh[Cc];
    __shared__ int   sh_alleq;

    const int b  = blockIdx.y;
    const int mt = blockIdx.x;
    const int t  = threadIdx.x;
    const int l  = t & 31;
    const int w  = t >> 5;
    const int msub  = w & 3;
    const int khalf = w >> 2;

    if (t < Cc) {
        float sg = sigma[t];
        sh_nh[t] = -0.5f * expf(-2.0f * sg) * LOG2E;
    }
    if (t == 0) {
        float s0 = sigma[0];
        int eq = 1;
        #pragma unroll
        for (int c = 1; c < Cc; c++) eq &= (sigma[c] == s0);
        sh_alleq = eq;
    }
    for (int i = t; i < NIN; i += GTHREADS) shx[i] = xc[(size_t)b * NIN + i];
    // load rt into swizzled smem (float4 granularity)
    {
        const float4* src = reinterpret_cast<const float4*>(g_rt + (size_t)b * NIN * Cc);
        for (int j = t; j < NIN * Cc / 4; j += GTHREADS) {
            int n  = j >> 2;
            int c4 = (j & 3) * 4;
            float4 v = src[j];
            int addr = (n >> 2) * 64 + (c4 >> 3) * 32 + (n & 3) * 8 + (c4 & 7);
            *reinterpret_cast<float4*>(&sB[addr]) = v;
        }
    }
    for (int i = t; i < OUTC * Cc; i += GTHREADS) shlw[i] = lw[i];
    __syncthreads();

    if (sh_alleq) {
        // ---- tf32 MMA fast path ----
        const float nh = sh_nh[0];
        const int mrow = mt * MTILE + msub * 16 + (l >> 2);
        const float xm0 = xt[(size_t)b * NOUT + mrow];
        const float xm1 = xt[(size_t)b * NOUT + mrow + 8];

        float D0[4] = {0.f, 0.f, 0.f, 0.f};
        float D1[4] = {0.f, 0.f, 0.f, 0.f};
        const int lof = (l & 3) * 8 + (l >> 2);
        const int kb  = khalf * (NIN / 2);

        #pragma unroll 4
        for (int ks = 0; ks < (NIN / 2) / 8; ks++) {
            const int k0 = kb + ks * 8;
            float xna = shx[k0 + (l & 3)];
            float xnb = shx[k0 + 4 + (l & 3)];
            unsigned A[4];
            float d;
            d = xm0 - xna; A[0] = f2tf32(ex2a(d * d * nh));
            d = xm1 - xna; A[1] = f2tf32(ex2a(d * d * nh));
            d = xm0 - xnb; A[2] = f2tf32(ex2a(d * d * nh));
            d = xm1 - xnb; A[3] = f2tf32(ex2a(d * d * nh));
            const int kbase = (k0 >> 2) * 64 + lof;
            unsigned b00 = __float_as_uint(sB[kbase]);
            unsigned b01 = __float_as_uint(sB[kbase + 64]);
            unsigned b10 = __float_as_uint(sB[kbase + 32]);
            unsigned b11 = __float_as_uint(sB[kbase + 96]);
            mma_tf32(D0, A, b00, b01);
            mma_tf32(D1, A, b10, b11);
        }

        // write k-half partial z to smem
        const int ml = msub * 16 + (l >> 2);
        const int c0 = (l & 3) * 2;
        *reinterpret_cast<float2*>(&zred[khalf][ml][c0])         = make_float2(D0[0], D0[1]);
        *reinterpret_cast<float2*>(&zred[khalf][ml + 8][c0])     = make_float2(D0[2], D0[3]);
        *reinterpret_cast<float2*>(&zred[khalf][ml][c0 + 8])     = make_float2(D1[0], D1[1]);
        *reinterpret_cast<float2*>(&zred[khalf][ml + 8][c0 + 8]) = make_float2(D1[2], D1[3]);
    } else {
        // ---- generic per-channel sigma fallback (correct, not fast) ----
        float nhc[8];
        const int chalf = l & 1;
        #pragma unroll
        for (int j = 0; j < 8; j++) nhc[j] = sh_nh[chalf * 8 + j];
        const int mloc = msub * 16 + (l >> 1);
        const float xm = xt[(size_t)b * NOUT + mt * MTILE + mloc];
        float acc[8];
        #pragma unroll
        for (int j = 0; j < 8; j++) acc[j] = 0.0f;
        const int nbeg = khalf * (NIN / 2);
        for (int n = nbeg; n < nbeg + NIN / 2; n++) {
            float dx = xm - shx[n];
            float d  = dx * dx;
            const int base = (n >> 2) * 64 + chalf * 32 + (n & 3) * 8;
            float4 ra = *reinterpret_cast<const float4*>(&sB[base]);
            float4 rb = *reinterpret_cast<const float4*>(&sB[base + 4]);
            acc[0] += ex2a(d * nhc[0]) * ra.x;
            acc[1] += ex2a(d * nhc[1]) * ra.y;
            acc[2] += ex2a(d * nhc[2]) * ra.z;
            acc[3] += ex2a(d * nhc[3]) * ra.w;
            acc[4] += ex2a(d * nhc[4]) * rb.x;
            acc[5] += ex2a(d * nhc[5]) * rb.y;
            acc[6] += ex2a(d * nhc[6]) * rb.z;
            acc[7] += ex2a(d * nhc[7]) * rb.w;
        }
        float* zp = &zred[khalf][mloc][chalf * 8];
        *reinterpret_cast<float4*>(zp)     = make_float4(acc[0], acc[1], acc[2], acc[3]);
        *reinterpret_cast<float4*>(zp + 4) = make_float4(acc[4], acc[5], acc[6], acc[7]);
    }
    __syncthreads();

    // linear C -> OUT_C + bias: thread t -> (ml = t>>2, 8 outputs at og=(t&3)*8)
    {
        const int ml = t >> 2;            // 0..63
        const int og = (t & 3) * 8;       // 0, 8, 16, 24
        float z[Cc];
        #pragma unroll
        for (int c = 0; c < Cc; c += 4) {
            float4 z0 = *reinterpret_cast<const float4*>(&zred[0][ml][c]);
            float4 z1 = *reinterpret_cast<const float4*>(&zred[1][ml][c]);
            z[c]     = z0.x + z1.x;
            z[c + 1] = z0.y + z1.y;
            z[c + 2] = z0.z + z1.z;
            z[c + 3] = z0.w + z1.w;
        }
        float o[8];
        #pragma unroll
        for (int k = 0; k < 8; k++) o[k] = __ldg(lb + og + k);
        #pragma unroll
        for (int c = 0; c < Cc; c++) {
            float zc = z[c];
            #pragma unroll
            for (int k = 0; k < 8; k++) o[k] += zc * shlw[(og + k) * Cc + c];
        }
        float* op = out + (((size_t)b * NOUT) + mt * MTILE + ml) * OUTC + og;
        *reinterpret_cast<float4*>(op)     = make_float4(o[0], o[1], o[2], o[3]);
        *reinterpret_cast<float4*>(op + 4) = make_float4(o[4], o[5], o[6], o[7]);
    }
}

// ---------------------------------------------------------------------------
// Launch. Inputs (metadata order):
// 0 r (8,16,512) | 1 x_context (8,512,1) | 2 y_context (unused) |
// 3 x_target (8,1024,1) | 4 conv_w (16,16,5) | 5 conv_b (16) |
// 6 sigma (16) | 7 lin_w (32,16) | 8 lin_b (32)  -> out (8,1024,32) f32
// ---------------------------------------------------------------------------
extern "C" void kernel_launch(void* const* d_in, const int* in_sizes, int n_in,
                              void* d_out, int out_size) {
    const float* r      = (const float*)d_in[0];
    const float* xc     = (const float*)d_in[1];
    const float* xt     = (const float*)d_in[3];
    const float* conv_w = (const float*)d_in[4];
    const float* conv_b = (const float*)d_in[5];
    const float* sigma  = (const float*)d_in[6];
    const float* lin_w  = (const float*)d_in[7];
    const float* lin_b  = (const float*)d_in[8];
    float* out = (float*)d_out;

    conv_kernel<<<dim3(NIN / CNTILE, Bq), CTHREADS>>>(r, conv_w, conv_b);
    gauss_mma_kernel<<<dim3(MT, Bq), GTHREADS>>>(xc, xt, sigma, lin_w, lin_b, out);
}

// round 8
// speedup vs baseline: 1.2605x; 1.0019x over previous
#include <cuda_runtime.h>
#include <cstdint>

// Problem constants
#define Bq     8
#define NIN    512
#define NOUT   1024
#define Cc     16
#define OUTC   32
#define KW     5

// Conv tiling
#define CNTILE 32
#define CTHREADS 128

// Gauss-MMA tiling
#define MTILE  64                 // m per block
#define MT     (NOUT / MTILE)     // 16
#define GTHREADS 512              // 16 warps: 4 m-subtiles x 4 k-quarters
#define KQ     4                  // k-quarters
#define KSTEPS ((NIN / KQ) / 8)   // 16 ksteps per warp

#define LOG2E 1.4426950408889634f

// conv output, stored PRE-SWIZZLED per batch in the gauss fragment layout:
// off(n,c) = (n>>2)*64 + (c>>3)*32 + (n&3)*8 + (c&7)
__device__ float g_rt[Bq * NIN * Cc];

__device__ __forceinline__ float ex2a(float x) {
    float r; asm("ex2.approx.f32 %0, %1;" : "=f"(r) : "f"(x)); return r;
}
__device__ __forceinline__ unsigned f2tf32(float x) {
    unsigned r; asm("cvt.rna.tf32.f32 %0, %1;" : "=r"(r) : "f"(x)); return r;
}
__device__ __forceinline__ void mma_tf32(float d[4], const unsigned a[4],
                                         unsigned b0, unsigned b1) {
    asm volatile(
        "mma.sync.aligned.m16n8k8.row.col.f32.tf32.tf32.f32 "
        "{%0,%1,%2,%3}, {%4,%5,%6,%7}, {%8,%9}, {%0,%1,%2,%3};"
        : "+f"(d[0]), "+f"(d[1]), "+f"(d[2]), "+f"(d[3])
        : "r"(a[0]), "r"(a[1]), "r"(a[2]), "r"(a[3]), "r"(b0), "r"(b1));
}

// ---------------------------------------------------------------------------
// Kernel 1: Conv1d (NCH, OIH, SAME pad=2) + bias -> g_rt (tf32-rounded,
// pre-swizzled). grid (16, 8) = 128 blocks, block 128.
// ---------------------------------------------------------------------------
__global__ void conv_kernel(const float* __restrict__ r,
                            const float* __restrict__ w,
                            const float* __restrict__ bias) {
    __shared__ float sr[Cc][CNTILE + 4];
    __shared__ float sws[Cc * KW * Cc];   // [ci][k][c_out]
    __shared__ float sb[Cc];

    const int b  = blockIdx.y;
    const int n0 = blockIdx.x * CNTILE;
    const int t  = threadIdx.x;

    for (int i = t; i < Cc * (CNTILE + 4); i += CTHREADS) {
        int ci = i / (CNTILE + 4);
        int j  = i % (CNTILE + 4);
        int n  = n0 + j - 2;
        sr[ci][j] = (n >= 0 && n < NIN) ? r[((size_t)b * Cc + ci) * NIN + n] : 0.0f;
    }
    for (int i = t; i < Cc * Cc * KW; i += CTHREADS) {
        int c  = i / (Cc * KW);
        int rm = i % (Cc * KW);
        int ci = rm / KW;
        int k  = rm % KW;
        sws[(ci * KW + k) * Cc + c] = w[i];
    }
    if (t < Cc) sb[t] = bias[t];
    __syncthreads();

    const int nl = t & (CNTILE - 1);
    const int cg = t >> 5;            // 0..3, channels cg*4..cg*4+3
    const int n  = n0 + nl;

    float4 a;
    a.x = sb[cg * 4 + 0]; a.y = sb[cg * 4 + 1];
    a.z = sb[cg * 4 + 2]; a.w = sb[cg * 4 + 3];

    #pragma unroll
    for (int k = 0; k < KW; k++) {
        #pragma unroll
        for (int ci = 0; ci < Cc; ci++) {
            float v = sr[ci][nl + k];
            float4 wv = *reinterpret_cast<const float4*>(&sws[(ci * KW + k) * Cc + cg * 4]);
            a.x += v * wv.x; a.y += v * wv.y; a.z += v * wv.z; a.w += v * wv.w;
        }
    }

    a.x = __uint_as_float(f2tf32(a.x));
    a.y = __uint_as_float(f2tf32(a.y));
    a.z = __uint_as_float(f2tf32(a.z));
    a.w = __uint_as_float(f2tf32(a.w));

    const int c4  = cg * 4;
    const int off = (n >> 2) * 64 + (c4 >> 3) * 32 + (n & 3) * 8 + (c4 & 7);
    *reinterpret_cast<float4*>(g_rt + (size_t)b * NIN * Cc + off) = a;
}

// ---------------------------------------------------------------------------
// Kernel 2: Gaussian transform as tf32 MMA + k-reduce + linear C->OUT_C.
// grid (MT, B) = (16, 8) = 128 blocks, block 512 (16 warps).
// Warp w: msub = w&3 (16 m rows), kq = w>>2 (128 n). Per kstep (8 n):
// thread computes its 4 A-fragment exps in registers; B fragments are
// conflict-free LDS.32 from the pre-swizzled rt copy.
// ---------------------------------------------------------------------------
__global__ void __launch_bounds__(GTHREADS, 1)
gauss_mma_kernel(const float* __restrict__ xc,
                 const float* __restrict__ xt,
                 const float* __restrict__ sigma,
                 const float* __restrict__ lw,
                 const float* __restrict__ lb,
                 float* __restrict__ out) {
    __shared__ __align__(16) float sB[NIN * Cc];          // 32 KB (pre-swizzled)
    __shared__ float shx[NIN];                            // 2 KB
    __shared__ __align__(16) float zred[KQ][MTILE][Cc];   // 16 KB partials
    __shared__ float shlw[OUTC * Cc];                     // 2 KB
    __shared__ float sh_nh[Cc];
    __shared__ int   sh_alleq;

    const int b  = blockIdx.y;
    const int mt = blockIdx.x;
    const int t  = threadIdx.x;
    const int l  = t & 31;
    const int w  = t >> 5;
    const int msub = w & 3;
    const int kq   = w >> 2;

    if (t < Cc) {
        float sg = sigma[t];
        sh_nh[t] = -0.5f * expf(-2.0f * sg) * LOG2E;
    }
    if (t == 0) {
        float s0 = sigma[0];
        int eq = 1;
        #pragma unroll
        for (int c = 1; c < Cc; c++) eq &= (sigma[c] == s0);
        sh_alleq = eq;
    }
    for (int i = t; i < NIN; i += GTHREADS) shx[i] = xc[(size_t)b * NIN + i];
    // straight coalesced copy (already swizzled)
    {
        const float4* src = reinterpret_cast<const float4*>(g_rt + (size_t)b * NIN * Cc);
        float4* dst = reinterpret_cast<float4*>(sB);
        #pragma unroll
        for (int j = t; j < NIN * Cc / 4; j += GTHREADS) dst[j] = src[j];
    }
    for (int i = t; i < OUTC * Cc; i += GTHREADS) shlw[i] = lw[i];
    __syncthreads();

    if (sh_alleq) {
        // ---- tf32 MMA fast path ----
        const float nh = sh_nh[0];
        const int mrow = mt * MTILE + msub * 16 + (l >> 2);
        const float xm0 = __ldg(xt + (size_t)b * NOUT + mrow);
        const float xm1 = __ldg(xt + (size_t)b * NOUT + mrow + 8);

        float D0[4] = {0.f, 0.f, 0.f, 0.f};
        float D1[4] = {0.f, 0.f, 0.f, 0.f};
        const int lof = (l & 3) * 8 + (l >> 2);
        const int kb  = kq * (NIN / KQ);

        #pragma unroll 4
        for (int ks = 0; ks < KSTEPS; ks++) {
            const int k0 = kb + ks * 8;
            float xna = shx[k0 + (l & 3)];
            float xnb = shx[k0 + 4 + (l & 3)];
            unsigned A[4];
            float d;
            d = xm0 - xna; A[0] = f2tf32(ex2a(d * d * nh));
            d = xm1 - xna; A[1] = f2tf32(ex2a(d * d * nh));
            d = xm0 - xnb; A[2] = f2tf32(ex2a(d * d * nh));
            d = xm1 - xnb; A[3] = f2tf32(ex2a(d * d * nh));
            const int kbase = (k0 >> 2) * 64 + lof;
            unsigned b00 = __float_as_uint(sB[kbase]);
            unsigned b01 = __float_as_uint(sB[kbase + 64]);
            unsigned b10 = __float_as_uint(sB[kbase + 32]);
            unsigned b11 = __float_as_uint(sB[kbase + 96]);
            mma_tf32(D0, A, b00, b01);
            mma_tf32(D1, A, b10, b11);
        }

        const int ml = msub * 16 + (l >> 2);
        const int c0 = (l & 3) * 2;
        *reinterpret_cast<float2*>(&zred[kq][ml][c0])         = make_float2(D0[0], D0[1]);
        *reinterpret_cast<float2*>(&zred[kq][ml + 8][c0])     = make_float2(D0[2], D0[3]);
        *reinterpret_cast<float2*>(&zred[kq][ml][c0 + 8])     = make_float2(D1[0], D1[1]);
        *reinterpret_cast<float2*>(&zred[kq][ml + 8][c0 + 8]) = make_float2(D1[2], D1[3]);
    } else {
        // ---- generic per-channel sigma fallback ----
        float nhc[8];
        const int chalf = l & 1;
        #pragma unroll
        for (int j = 0; j < 8; j++) nhc[j] = sh_nh[chalf * 8 + j];
        const int mloc = msub * 16 + (l >> 1);
        const float xm = __ldg(xt + (size_t)b * NOUT + mt * MTILE + mloc);
        float acc[8];
        #pragma unroll
        for (int j = 0; j < 8; j++) acc[j] = 0.0f;
        const int nbeg = kq * (NIN / KQ);
        for (int n = nbeg; n < nbeg + NIN / KQ; n++) {
            float dx = xm - shx[n];
            float d  = dx * dx;
            const int base = (n >> 2) * 64 + chalf * 32 + (n & 3) * 8;
            float4 ra = *reinterpret_cast<const float4*>(&sB[base]);
            float4 rb = *reinterpret_cast<const float4*>(&sB[base + 4]);
            acc[0] += ex2a(d * nhc[0]) * ra.x;
            acc[1] += ex2a(d * nhc[1]) * ra.y;
            acc[2] += ex2a(d * nhc[2]) * ra.z;
            acc[3] += ex2a(d * nhc[3]) * ra.w;
            acc[4] += ex2a(d * nhc[4]) * rb.x;
            acc[5] += ex2a(d * nhc[5]) * rb.y;
            acc[6] += ex2a(d * nhc[6]) * rb.z;
            acc[7] += ex2a(d * nhc[7]) * rb.w;
        }
        float* zp = &zred[kq][mloc][chalf * 8];
        *reinterpret_cast<float4*>(zp)     = make_float4(acc[0], acc[1], acc[2], acc[3]);
        *reinterpret_cast<float4*>(zp + 4) = make_float4(acc[4], acc[5], acc[6], acc[7]);
    }
    __syncthreads();

    // linear C -> OUT_C + bias: thread t -> (ml = t>>3, 4 outputs at og=(t&7)*4)
    {
        const int ml = t >> 3;            // 0..63
        const int og = (t & 7) * 4;       // 0..28
        float z[Cc];
        #pragma unroll
        for (int c = 0; c < Cc; c += 4) {
            float4 z0 = *reinterpret_cast<const float4*>(&zred[0][ml][c]);
            float4 z1 = *reinterpret_cast<const float4*>(&zred[1][ml][c]);
            float4 z2 = *reinterpret_cast<const float4*>(&zred[2][ml][c]);
            float4 z3 = *reinterpret_cast<const float4*>(&zred[3][ml][c]);
            z[c]     = (z0.x + z1.x) + (z2.x + z3.x);
            z[c + 1] = (z0.y + z1.y) + (z2.y + z3.y);
            z[c + 2] = (z0.z + z1.z) + (z2.z + z3.z);
            z[c + 3] = (z0.w + z1.w) + (z2.w + z3.w);
        }
        float4 o4;
        o4.x = __ldg(lb + og + 0); o4.y = __ldg(lb + og + 1);
        o4.z = __ldg(lb + og + 2); o4.w = __ldg(lb + og + 3);
        #pragma unroll
        for (int c = 0; c < Cc; c++) {
            float zc = z[c];
            o4.x += zc * shlw[(og + 0) * Cc + c];
            o4.y += zc * shlw[(og + 1) * Cc + c];
            o4.z += zc * shlw[(og + 2) * Cc + c];
            o4.w += zc * shlw[(og + 3) * Cc + c];
        }
        *reinterpret_cast<float4*>(
            out + (((size_t)b * NOUT) + mt * MTILE + ml) * OUTC + og) = o4;
    }
}

// ---------------------------------------------------------------------------
// Launch. Inputs (metadata order):
// 0 r (8,16,512) | 1 x_context (8,512,1) | 2 y_context (unused) |
// 3 x_target (8,1024,1) | 4 conv_w (16,16,5) | 5 conv_b (16) |
// 6 sigma (16) | 7 lin_w (32,16) | 8 lin_b (32)  -> out (8,1024,32) f32
// ---------------------------------------------------------------------------
extern "C" void kernel_launch(void* const* d_in, const int* in_sizes, int n_in,
                              void* d_out, int out_size) {
    const float* r      = (const float*)d_in[0];
    const float* xc     = (const float*)d_in[1];
    const float* xt     = (const float*)d_in[3];
    const float* conv_w = (const float*)d_in[4];
    const float* conv_b = (const float*)d_in[5];
    const float* sigma  = (const float*)d_in[6];
    const float* lin_w  = (const float*)d_in[7];
    const float* lin_b  = (const float*)d_in[8];
    float* out = (float*)d_out;

    conv_kernel<<<dim3(NIN / CNTILE, Bq), CTHREADS>>>(r, conv_w, conv_b);
    gauss_mma_kernel<<<dim3(MT, Bq), GTHREADS>>>(xc, xt, sigma, lin_w, lin_b, out);
}